// round 2
// baseline (speedup 1.0000x reference)
#include <cuda_runtime.h>
#include <cuda_bf16.h>
#include <cstdint>

// BlockAttnRes: per-token block attention over N=9 source rows of D=512.
//   score_n = dot(src_n, w) / sqrt(mean(src_n^2)+1e-6),  alpha = softmax(score),
//   h = sum_n alpha_n * src_n.
//
// R2 design: one CTA per token; the 18 KB token tile is fetched with a single
// cp.async.bulk (TMA) into SMEM instead of per-warp LDG into registers.
//   - regs drop ~69 -> ~48  => occupancy 28 -> ~40 warps/SM
//   - DRAM bytes delivered via the bulk path (no L1tex wavefront queue)
//   - softmax computed redundantly by every thread (one barrier total)

#define NN 9
#define DD 512
#define THREADS 128
#define TILE_BYTES (NN * DD * 4)   // 18432

__device__ __forceinline__ uint32_t smem_u32(const void* p) {
    return (uint32_t)__cvta_generic_to_shared(p);
}

__global__ __launch_bounds__(THREADS, 10)
void blockattn_kernel(const float* __restrict__ src,
                      const float* __restrict__ queries,
                      const int*   __restrict__ layer_idx,
                      float*       __restrict__ out)
{
    __shared__ __align__(16) float sv[NN * DD];      // 18432 B token tile
    __shared__ __align__(8)  uint64_t mbar;
    __shared__ float s_ss[NN][4];
    __shared__ float s_dt[NN][4];

    const int tid  = threadIdx.x;
    const int lane = tid & 31;
    const int warp = tid >> 5;
    const long long token = blockIdx.x;

    const uint32_t bar = smem_u32(&mbar);

    if (tid == 0) {
        asm volatile("mbarrier.init.shared.b64 [%0], 1;" :: "r"(bar) : "memory");
    }
    __syncthreads();

    if (tid == 0) {
        asm volatile("mbarrier.arrive.expect_tx.shared.b64 _, [%0], %1;"
                     :: "r"(bar), "r"((uint32_t)TILE_BYTES) : "memory");
        asm volatile(
            "cp.async.bulk.shared::cta.global.mbarrier::complete_tx::bytes "
            "[%0], [%1], %2, [%3];"
            :: "r"(smem_u32(sv)),
               "l"(src + token * (long long)(NN * DD)),
               "r"((uint32_t)TILE_BYTES),
               "r"(bar)
            : "memory");
    }

    // Query slice while the bulk copy is in flight (L2-resident broadcast).
    const int li = *layer_idx;
    const float4 w4 = reinterpret_cast<const float4*>(queries + (long long)li * DD)[tid];

    // Wait for TMA completion (phase 0 — barrier freshly initialized each launch).
    {
        uint32_t done;
        asm volatile(
            "{\n\t.reg .pred p;\n\t"
            "mbarrier.try_wait.parity.shared.b64 p, [%1], 0;\n\t"
            "selp.b32 %0, 1, 0, p;\n\t}"
            : "=r"(done) : "r"(bar) : "memory");
        while (!done) {
            asm volatile(
                "{\n\t.reg .pred p;\n\t"
                "mbarrier.try_wait.parity.shared.b64 p, [%1], 0, 0x989680;\n\t"
                "selp.b32 %0, 1, 0, p;\n\t}"
                : "=r"(done) : "r"(bar) : "memory");
        }
    }

    // ---- Phase 1: per-thread partials from SMEM (conflict-free LDS.128) ----
    const float4* svv = reinterpret_cast<const float4*>(sv);
    float ss[NN], dt[NN];
#pragma unroll
    for (int n = 0; n < NN; n++) {
        const float4 a = svv[n * (DD / 4) + tid];
        ss[n] = a.x * a.x + a.y * a.y + a.z * a.z + a.w * a.w;
        dt[n] = a.x * w4.x + a.y * w4.y + a.z * w4.z + a.w * w4.w;
    }

#pragma unroll
    for (int n = 0; n < NN; n++) {
#pragma unroll
        for (int o = 16; o > 0; o >>= 1) {
            ss[n] += __shfl_xor_sync(0xffffffffu, ss[n], o);
            dt[n] += __shfl_xor_sync(0xffffffffu, dt[n], o);
        }
    }

    if (lane == 0) {
#pragma unroll
        for (int n = 0; n < NN; n++) {
            s_ss[n][warp] = ss[n];
            s_dt[n][warp] = dt[n];
        }
    }
    __syncthreads();

    // ---- Softmax: computed redundantly by every thread (broadcast LDS) ----
    float alpha[NN];
    {
        float mx = -3.4e38f;
#pragma unroll
        for (int n = 0; n < NN; n++) {
            const float S  = s_ss[n][0] + s_ss[n][1] + s_ss[n][2] + s_ss[n][3];
            const float Dt = s_dt[n][0] + s_dt[n][1] + s_dt[n][2] + s_dt[n][3];
            alpha[n] = Dt * rsqrtf(S * (1.0f / DD) + 1e-6f);
            mx = fmaxf(mx, alpha[n]);
        }
        float sum = 0.0f;
#pragma unroll
        for (int n = 0; n < NN; n++) {
            alpha[n] = __expf(alpha[n] - mx);
            sum += alpha[n];
        }
        const float inv = 1.0f / sum;
#pragma unroll
        for (int n = 0; n < NN; n++)
            alpha[n] *= inv;
    }

    // ---- Phase 2: weighted sum from SMEM ----
    float4 o = make_float4(0.f, 0.f, 0.f, 0.f);
#pragma unroll
    for (int n = 0; n < NN; n++) {
        const float4 a = svv[n * (DD / 4) + tid];
        o.x += alpha[n] * a.x;
        o.y += alpha[n] * a.y;
        o.z += alpha[n] * a.z;
        o.w += alpha[n] * a.w;
    }

    reinterpret_cast<float4*>(out + token * (long long)DD)[tid] = o;
}

extern "C" void kernel_launch(void* const* d_in, const int* in_sizes, int n_in,
                              void* d_out, int out_size)
{
    const float* src     = (const float*)d_in[0];
    const float* queries = (const float*)d_in[1];
    const int*   lidx    = (const int*)d_in[2];
    float*       out     = (float*)d_out;

    const int tokens = in_sizes[0] / (NN * DD);   // B*T = 32768
    blockattn_kernel<<<tokens, THREADS>>>(src, queries, lidx, out);
}

// round 3
// speedup vs baseline: 1.1278x; 1.1278x over previous
#include <cuda_runtime.h>
#include <cuda_bf16.h>

// BlockAttnRes: per-token block attention over N=9 source rows of D=512.
//   score_n = dot(src_n, w) / sqrt(mean(src_n^2)+1e-6),  alpha = softmax(score),
//   h = sum_n alpha_n * src_n.
//
// R3: back to R1's register-resident single-DRAM-read design (R2's TMA+SMEM
// version made the smem port co-binding and regressed). Tuned for occupancy:
//   - __launch_bounds__(128, 8): 8 CTAs/SM (was 7) -> +14% loads in flight
//   - per-row partials reduced+stored inside the row loop (short-lived regs)
//   - single __syncthreads: softmax recomputed redundantly per thread
//   - streaming store for the 67 MB output

#define NN 9
#define DD 512
#define THREADS 128

__global__ __launch_bounds__(THREADS, 8)
void blockattn_kernel(const float* __restrict__ src,
                      const float* __restrict__ queries,
                      const int*   __restrict__ layer_idx,
                      float*       __restrict__ out)
{
    __shared__ float s_ss[NN][4];
    __shared__ float s_dt[NN][4];

    const int tid  = threadIdx.x;
    const int lane = tid & 31;
    const int warp = tid >> 5;
    const long long token = blockIdx.x;

    const float4* base = reinterpret_cast<const float4*>(src + token * (long long)(NN * DD));

    const int li = __ldg(layer_idx);
    const float4 w4 = __ldg(reinterpret_cast<const float4*>(queries + (long long)li * DD) + tid);

    // ---- Front-batched loads: all 9 rows into registers (single DRAM read) ----
    float4 v[NN];
#pragma unroll
    for (int n = 0; n < NN; n++)
        v[n] = __ldg(base + n * (DD / 4) + tid);

    // ---- Per-row partials: compute, warp-reduce, stash — regs die per row ----
#pragma unroll
    for (int n = 0; n < NN; n++) {
        const float4 a = v[n];
        float ssn = a.x * a.x + a.y * a.y + a.z * a.z + a.w * a.w;
        float dtn = a.x * w4.x + a.y * w4.y + a.z * w4.z + a.w * w4.w;
#pragma unroll
        for (int o = 16; o > 0; o >>= 1) {
            ssn += __shfl_xor_sync(0xffffffffu, ssn, o);
            dtn += __shfl_xor_sync(0xffffffffu, dtn, o);
        }
        if (lane == 0) {
            s_ss[n][warp] = ssn;
            s_dt[n][warp] = dtn;
        }
    }
    __syncthreads();

    // ---- Softmax over 9, computed redundantly by every thread (broadcast LDS) ----
    float alpha[NN];
    {
        float mx = -3.4e38f;
#pragma unroll
        for (int n = 0; n < NN; n++) {
            const float S  = s_ss[n][0] + s_ss[n][1] + s_ss[n][2] + s_ss[n][3];
            const float Dt = s_dt[n][0] + s_dt[n][1] + s_dt[n][2] + s_dt[n][3];
            alpha[n] = Dt * rsqrtf(S * (1.0f / DD) + 1e-6f);
            mx = fmaxf(mx, alpha[n]);
        }
        float sum = 0.0f;
#pragma unroll
        for (int n = 0; n < NN; n++) {
            alpha[n] = __expf(alpha[n] - mx);
            sum += alpha[n];
        }
        const float inv = 1.0f / sum;
#pragma unroll
        for (int n = 0; n < NN; n++)
            alpha[n] *= inv;
    }

    // ---- Weighted sum from register-resident rows; streaming store ----
    float4 o = make_float4(0.f, 0.f, 0.f, 0.f);
#pragma unroll
    for (int n = 0; n < NN; n++) {
        o.x += alpha[n] * v[n].x;
        o.y += alpha[n] * v[n].y;
        o.z += alpha[n] * v[n].z;
        o.w += alpha[n] * v[n].w;
    }

    __stcs(reinterpret_cast<float4*>(out + token * (long long)DD) + tid, o);
}

extern "C" void kernel_launch(void* const* d_in, const int* in_sizes, int n_in,
                              void* d_out, int out_size)
{
    const float* src     = (const float*)d_in[0];
    const float* queries = (const float*)d_in[1];
    const int*   lidx    = (const int*)d_in[2];
    float*       out     = (float*)d_out;

    const int tokens = in_sizes[0] / (NN * DD);   // B*T = 32768
    blockattn_kernel<<<tokens, THREADS>>>(src, queries, lidx, out);
}